// round 3
// baseline (speedup 1.0000x reference)
#include <cuda_runtime.h>
#include <math.h>

#define BN   20800
#define T_   24
#define F_   64
#define H_   128
#define H2_  256
#define H3_  384
#define TR   48            // rows per CTA
#define TRP2 98            // padded duplicated smem row stride (2*TR + 2, even)
#define RPT  6             // rows per thread
#define NCTA ((BN + TR - 1) / TR)   // 434

typedef unsigned long long ull;

// packed f32x2 FMA: d = a*b + c elementwise on two packed fp32
#define FMA2(d, a, b, c) \
    asm("fma.rn.f32x2 %0, %1, %2, %3;" : "=l"(d) : "l"(a), "l"(b), "l"(c))
#define UNPK2(lo, hi, v) \
    asm("mov.b64 {%0, %1}, %2;" : "=f"(lo), "=f"(hi) : "l"(v))
#define PACK2(d, lo, hi) \
    asm("mov.b64 %0, {%1, %2};" : "=l"(d) : "f"(lo), "f"(hi))

// scratch: layer-0 output sequence [BN][T][H]
__device__ float g_seq1[(size_t)BN * T_ * H_];
// pre-transposed weights: [k][c]
__device__ float g_wihT[F_ * H3_];
__device__ float g_whhT[H_ * H3_];
__device__ float g_gwT[H2_ * H2_];
__device__ float g_owT[H2_ * H_];

__global__ void transpose_weights(const float* __restrict__ w_ih,
                                  const float* __restrict__ w_hh,
                                  const float* __restrict__ gate_w,
                                  const float* __restrict__ out_w)
{
    int idx = blockIdx.x * blockDim.x + threadIdx.x;
    if (idx < H3_ * F_)  { int c = idx / F_,  k = idx % F_;  g_wihT[k * H3_ + c] = w_ih[idx]; }
    if (idx < H3_ * H_)  { int c = idx / H_,  k = idx % H_;  g_whhT[k * H3_ + c] = w_hh[idx]; }
    if (idx < H2_ * H2_) { int c = idx / H2_, k = idx % H2_; g_gwT[k * H2_ + c] = gate_w[idx]; }
    if (idx < H_ * H2_)  { int c = idx / H2_, k = idx % H2_; g_owT[k * H_ + c] = out_w[idx]; }
}

__device__ __forceinline__ float sigmoidf_(float v) {
    return __fdividef(1.0f, 1.0f + __expf(-v));
}
__device__ __forceinline__ float tanhf_(float v) {
    return __fdividef(2.0f, 1.0f + __expf(-2.0f * v)) - 1.0f;
}

// acc2[i][jp] (+)= (A[k][2(row0+i)], A[k][2(row0+i)+1]) * (W[k][c4+2jp], W[k][c4+2jp+1])
// A: smem, value-duplicated layout [k][2r / 2r+1] -> broadcast LDS.64 gives (a,a).
// Wt: gmem transposed weights [k][c], offset to c4; LDG.128 -> two packed f32x2.
template<int K>
__device__ __forceinline__ void mm_acc2(ull acc[RPT][2],
                                        const float* __restrict__ A,
                                        const float* __restrict__ Wt,
                                        int ldw, int row0d)
{
    #pragma unroll 8
    for (int k = 0; k < K; ++k) {
        ulonglong2 w = __ldg(reinterpret_cast<const ulonglong2*>(Wt + (size_t)k * ldw));
        const float* ap = A + k * TRP2 + row0d;
        ull a2[RPT];
        #pragma unroll
        for (int i = 0; i < RPT; ++i)
            a2[i] = *reinterpret_cast<const ull*>(ap + 2 * i);
        #pragma unroll
        for (int i = 0; i < RPT; ++i) {
            FMA2(acc[i][0], a2[i], w.x, acc[i][0]);
            FMA2(acc[i][1], a2[i], w.y, acc[i][1]);
        }
    }
}

#define ZERO_ACC2(A)                                  \
    _Pragma("unroll")                                 \
    for (int i = 0; i < RPT; ++i) {                   \
        (A)[i][0] = 0ULL; (A)[i][1] = 0ULL;           \
    }

#define UNPACK_ACC(F, A)                              \
    _Pragma("unroll")                                 \
    for (int i = 0; i < RPT; ++i) {                   \
        UNPK2((F)[i][0], (F)[i][1], (A)[i][0]);       \
        UNPK2((F)[i][2], (F)[i][3], (A)[i][1]);       \
    }

// ---------------- Layer 0: torch GRUCell over T steps ----------------
__global__ __launch_bounds__(256, 1)
void gru_layer0(const float* __restrict__ x,
                const float* __restrict__ b_ih,
                const float* __restrict__ b_hh)
{
    __shared__ __align__(16) float x_s[F_ * TRP2];   // x_t transposed+duplicated [f][2r]
    __shared__ __align__(16) float h_s[H_ * TRP2];   // h transposed+duplicated [k][2r]

    const int tid   = threadIdx.x;
    const int rg    = tid >> 5, cg = tid & 31;
    const int row0  = rg * RPT;
    const int row0d = row0 * 2;
    const int c4    = cg * 4;
    const int bn0   = blockIdx.x * TR;

    for (int i = tid; i < H_ * TRP2; i += 256) h_s[i] = 0.0f;

    float br[4], bz[4], bi_n[4], bh_n[4];
    #pragma unroll
    for (int j = 0; j < 4; ++j) {
        br[j]   = b_ih[c4 + j]        + b_hh[c4 + j];
        bz[j]   = b_ih[H_ + c4 + j]   + b_hh[H_ + c4 + j];
        bi_n[j] = b_ih[2 * H_ + c4 + j];
        bh_n[j] = b_hh[2 * H_ + c4 + j];
    }

    for (int t = 0; t < T_; ++t) {
        // load x_t tile (48 rows x 64 f), transposed + duplicated into smem
        #pragma unroll
        for (int u = 0; u < 3; ++u) {
            int idx = tid + u * 256;       // 0..767 float4 slots
            int r = idx >> 4;
            int f = (idx & 15) * 4;
            float4 v = make_float4(0.f, 0.f, 0.f, 0.f);
            int bn = bn0 + r;
            if (bn < BN)
                v = *reinterpret_cast<const float4*>(x + ((size_t)bn * T_ + t) * F_ + f);
            ull p;
            PACK2(p, v.x, v.x); *reinterpret_cast<ull*>(&x_s[(f + 0) * TRP2 + 2 * r]) = p;
            PACK2(p, v.y, v.y); *reinterpret_cast<ull*>(&x_s[(f + 1) * TRP2 + 2 * r]) = p;
            PACK2(p, v.z, v.z); *reinterpret_cast<ull*>(&x_s[(f + 2) * TRP2 + 2 * r]) = p;
            PACK2(p, v.w, v.w); *reinterpret_cast<ull*>(&x_s[(f + 3) * TRP2 + 2 * r]) = p;
        }
        __syncthreads();   // x_s ready; h_s writes from prev step visible

        ull accA[RPT][2], accB[RPT][2];
        float fA[RPT][4], fB[RPT][4];

        // r gate (cols 0..127): gi + gh
        ZERO_ACC2(accA); ZERO_ACC2(accB);
        mm_acc2<F_>(accA, x_s, g_wihT + c4, H3_, row0d);
        mm_acc2<H_>(accB, h_s, g_whhT + c4, H3_, row0d);
        UNPACK_ACC(fA, accA); UNPACK_ACC(fB, accB);
        float rr[RPT][4];
        #pragma unroll
        for (int i = 0; i < RPT; ++i)
            #pragma unroll
            for (int j = 0; j < 4; ++j)
                rr[i][j] = sigmoidf_(fA[i][j] + fB[i][j] + br[j]);

        // z gate (cols 128..255)
        ZERO_ACC2(accA); ZERO_ACC2(accB);
        mm_acc2<F_>(accA, x_s, g_wihT + H_ + c4, H3_, row0d);
        mm_acc2<H_>(accB, h_s, g_whhT + H_ + c4, H3_, row0d);
        UNPACK_ACC(fA, accA); UNPACK_ACC(fB, accB);
        float zz[RPT][4];
        #pragma unroll
        for (int i = 0; i < RPT; ++i)
            #pragma unroll
            for (int j = 0; j < 4; ++j)
                zz[i][j] = sigmoidf_(fA[i][j] + fB[i][j] + bz[j]);

        // n gate (cols 256..383): keep gi and gh separate
        ZERO_ACC2(accA); ZERO_ACC2(accB);
        mm_acc2<F_>(accA, x_s, g_wihT + 2 * H_ + c4, H3_, row0d);
        mm_acc2<H_>(accB, h_s, g_whhT + 2 * H_ + c4, H3_, row0d);
        UNPACK_ACC(fA, accA); UNPACK_ACC(fB, accB);

        float hn[RPT][4];
        #pragma unroll
        for (int i = 0; i < RPT; ++i)
            #pragma unroll
            for (int j = 0; j < 4; ++j) {
                float hold = h_s[(c4 + j) * TRP2 + 2 * (row0 + i)];
                float n = tanhf_(fA[i][j] + bi_n[j] + rr[i][j] * (fB[i][j] + bh_n[j]));
                hn[i][j] = (1.f - zz[i][j]) * n + zz[i][j] * hold;
            }
        __syncthreads();   // all reads of h_s / x_s done

        #pragma unroll
        for (int i = 0; i < RPT; ++i) {
            #pragma unroll
            for (int j = 0; j < 4; ++j) {
                ull p;
                PACK2(p, hn[i][j], hn[i][j]);
                *reinterpret_cast<ull*>(&h_s[(c4 + j) * TRP2 + 2 * (row0 + i)]) = p;
            }
            int bn = bn0 + row0 + i;
            if (bn < BN)
                *reinterpret_cast<float4*>(g_seq1 + ((size_t)bn * T_ + t) * H_ + c4)
                    = make_float4(hn[i][0], hn[i][1], hn[i][2], hn[i][3]);
        }
        // next iteration's post-load __syncthreads orders these writes vs. reads
    }
}

// ---------------- Layer 1: custom GRUCell over T steps ----------------
__global__ __launch_bounds__(256, 1)
void gru_layer1(const float* __restrict__ gate_b,
                const float* __restrict__ out_b,
                float* __restrict__ out)
{
    __shared__ __align__(16) float x_s[H_ * TRP2];
    __shared__ __align__(16) float h_s[H_ * TRP2];
    __shared__ __align__(16) float rh_s[H_ * TRP2];

    const int tid   = threadIdx.x;
    const int rg    = tid >> 5, cg = tid & 31;
    const int row0  = rg * RPT;
    const int row0d = row0 * 2;
    const int c4    = cg * 4;
    const int bn0   = blockIdx.x * TR;

    for (int i = tid; i < H_ * TRP2; i += 256) h_s[i] = 0.0f;

    float bgr[4], bgz[4], bo[4];
    #pragma unroll
    for (int j = 0; j < 4; ++j) {
        bgr[j] = gate_b[c4 + j];
        bgz[j] = gate_b[H_ + c4 + j];
        bo[j]  = out_b[c4 + j];
    }

    for (int t = 0; t < T_; ++t) {
        // load x_t = seq1[:, t, :] tile (48 x 128), transposed + duplicated
        #pragma unroll
        for (int u = 0; u < 6; ++u) {
            int idx = tid + u * 256;    // 0..1535 float4 slots
            int r = idx >> 5;
            int f = (idx & 31) * 4;
            float4 v = make_float4(0.f, 0.f, 0.f, 0.f);
            int bn = bn0 + r;
            if (bn < BN)
                v = *reinterpret_cast<const float4*>(g_seq1 + ((size_t)bn * T_ + t) * H_ + f);
            ull p;
            PACK2(p, v.x, v.x); *reinterpret_cast<ull*>(&x_s[(f + 0) * TRP2 + 2 * r]) = p;
            PACK2(p, v.y, v.y); *reinterpret_cast<ull*>(&x_s[(f + 1) * TRP2 + 2 * r]) = p;
            PACK2(p, v.z, v.z); *reinterpret_cast<ull*>(&x_s[(f + 2) * TRP2 + 2 * r]) = p;
            PACK2(p, v.w, v.w); *reinterpret_cast<ull*>(&x_s[(f + 3) * TRP2 + 2 * r]) = p;
        }
        __syncthreads();

        ull acc2[RPT][2];
        float fA[RPT][4];

        // r gate (cols 0..127 of gates), K = 256 split as x-part + h-part
        ZERO_ACC2(acc2);
        mm_acc2<H_>(acc2, x_s, g_gwT + c4, H2_, row0d);
        mm_acc2<H_>(acc2, h_s, g_gwT + (size_t)H_ * H2_ + c4, H2_, row0d);
        UNPACK_ACC(fA, acc2);
        float rr[RPT][4];
        #pragma unroll
        for (int i = 0; i < RPT; ++i)
            #pragma unroll
            for (int j = 0; j < 4; ++j)
                rr[i][j] = sigmoidf_(fA[i][j] + bgr[j]);

        // z gate (cols 128..255)
        ZERO_ACC2(acc2);
        mm_acc2<H_>(acc2, x_s, g_gwT + H_ + c4, H2_, row0d);
        mm_acc2<H_>(acc2, h_s, g_gwT + (size_t)H_ * H2_ + H_ + c4, H2_, row0d);
        UNPACK_ACC(fA, acc2);
        float zz[RPT][4];
        #pragma unroll
        for (int i = 0; i < RPT; ++i)
            #pragma unroll
            for (int j = 0; j < 4; ++j)
                zz[i][j] = sigmoidf_(fA[i][j] + bgz[j]);

        // r * h into smem (thread's r-cols == its h-feature cols)
        float hold[RPT][4];
        #pragma unroll
        for (int i = 0; i < RPT; ++i)
            #pragma unroll
            for (int j = 0; j < 4; ++j) {
                hold[i][j] = h_s[(c4 + j) * TRP2 + 2 * (row0 + i)];
                float rh = rr[i][j] * hold[i][j];
                ull p;
                PACK2(p, rh, rh);
                *reinterpret_cast<ull*>(&rh_s[(c4 + j) * TRP2 + 2 * (row0 + i)]) = p;
            }
        __syncthreads();   // rh_s ready; all h_s reads done

        // candidate: [x | r*h] @ out_w^T  (cols 0..127)
        ZERO_ACC2(acc2);
        mm_acc2<H_>(acc2, x_s,  g_owT + c4, H_, row0d);
        mm_acc2<H_>(acc2, rh_s, g_owT + (size_t)H_ * H_ + c4, H_, row0d);
        UNPACK_ACC(fA, acc2);

        float hn[RPT][4];
        #pragma unroll
        for (int i = 0; i < RPT; ++i)
            #pragma unroll
            for (int j = 0; j < 4; ++j) {
                float cand = tanhf_(fA[i][j] + bo[j]);
                hn[i][j] = zz[i][j] * hold[i][j] + (1.f - zz[i][j]) * cand;
            }
        __syncthreads();   // all x_s / rh_s reads done before overwrites

        #pragma unroll
        for (int i = 0; i < RPT; ++i) {
            #pragma unroll
            for (int j = 0; j < 4; ++j) {
                ull p;
                PACK2(p, hn[i][j], hn[i][j]);
                *reinterpret_cast<ull*>(&h_s[(c4 + j) * TRP2 + 2 * (row0 + i)]) = p;
            }
            int bn = bn0 + row0 + i;
            if (bn < BN)
                *reinterpret_cast<float4*>(out + ((size_t)bn * T_ + t) * H_ + c4)
                    = make_float4(hn[i][0], hn[i][1], hn[i][2], hn[i][3]);
        }
    }
}

extern "C" void kernel_launch(void* const* d_in, const int* in_sizes, int n_in,
                              void* d_out, int out_size)
{
    const float* x      = (const float*)d_in[0];
    const float* w_ih   = (const float*)d_in[1];
    const float* w_hh   = (const float*)d_in[2];
    const float* b_ih   = (const float*)d_in[3];
    const float* b_hh   = (const float*)d_in[4];
    const float* gate_w = (const float*)d_in[5];
    const float* gate_b = (const float*)d_in[6];
    const float* out_w  = (const float*)d_in[7];
    const float* out_b  = (const float*)d_in[8];
    float* out = (float*)d_out;

    transpose_weights<<<(H2_ * H2_ + 255) / 256, 256>>>(w_ih, w_hh, gate_w, out_w);
    gru_layer0<<<NCTA, 256>>>(x, b_ih, b_hh);
    gru_layer1<<<NCTA, 256>>>(gate_b, out_b, out);
}

// round 4
// speedup vs baseline: 1.1028x; 1.1028x over previous
#include <cuda_runtime.h>
#include <math.h>

#define BN   20800
#define T_   24
#define F_   64
#define H_   128
#define H2_  256
#define H3_  384
#define TR   48            // rows per CTA
#define TRP2 98            // padded duplicated smem row stride (2*TR + 2, even)
#define RPT  6             // rows per thread
#define NCTA ((BN + TR - 1) / TR)   // 434

typedef unsigned long long ull;

// packed f32x2 FMA: d = a*b + c elementwise on two packed fp32
#define FMA2(d, a, b, c) \
    asm("fma.rn.f32x2 %0, %1, %2, %3;" : "=l"(d) : "l"(a), "l"(b), "l"(c))
#define UNPK2(lo, hi, v) \
    asm("mov.b64 {%0, %1}, %2;" : "=f"(lo), "=f"(hi) : "l"(v))
#define PACK2(d, lo, hi) \
    asm("mov.b64 %0, {%1, %2};" : "=l"(d) : "f"(lo), "f"(hi))

// scratch: layer-0 output sequence [BN][T][H]
__device__ float g_seq1[(size_t)BN * T_ * H_];
// pre-transposed weights: [k][c]
__device__ float g_wihT[F_ * H3_];
__device__ float g_whhT[H_ * H3_];
__device__ float g_gwT[H2_ * H2_];
__device__ float g_owT[H2_ * H_];

__global__ void transpose_weights(const float* __restrict__ w_ih,
                                  const float* __restrict__ w_hh,
                                  const float* __restrict__ gate_w,
                                  const float* __restrict__ out_w)
{
    int idx = blockIdx.x * blockDim.x + threadIdx.x;
    if (idx < H3_ * F_)  { int c = idx / F_,  k = idx % F_;  g_wihT[k * H3_ + c] = w_ih[idx]; }
    if (idx < H3_ * H_)  { int c = idx / H_,  k = idx % H_;  g_whhT[k * H3_ + c] = w_hh[idx]; }
    if (idx < H2_ * H2_) { int c = idx / H2_, k = idx % H2_; g_gwT[k * H2_ + c] = gate_w[idx]; }
    if (idx < H_ * H2_)  { int c = idx / H2_, k = idx % H2_; g_owT[k * H_ + c] = out_w[idx]; }
}

__device__ __forceinline__ float sigmoidf_(float v) {
    return __fdividef(1.0f, 1.0f + __expf(-v));
}
__device__ __forceinline__ float tanhf_(float v) {
    return __fdividef(2.0f, 1.0f + __expf(-2.0f * v)) - 1.0f;
}

#define ZERO6x2(A)                                    \
    _Pragma("unroll")                                 \
    for (int i = 0; i < RPT; ++i) {                   \
        (A)[i][0] = 0ULL; (A)[i][1] = 0ULL;           \
    }

#define UNPACK6x2(F, A)                               \
    _Pragma("unroll")                                 \
    for (int i = 0; i < RPT; ++i) {                   \
        UNPK2((F)[i][0], (F)[i][1], (A)[i][0]);       \
        UNPK2((F)[i][2], (F)[i][3], (A)[i][1]);       \
    }

// ---------------- Layer 0: torch GRUCell over T steps ----------------
// Fused-gate GEMM: one pass over x (K=64) and one over h (K=128); each k
// loads the activation ONCE (6 broadcast LDS.64) and three weight float4s
// (r/z/n column blocks). r,z accumulate x+h jointly; n kept split.
__global__ __launch_bounds__(256, 1)
void gru_layer0(const float* __restrict__ x,
                const float* __restrict__ b_ih,
                const float* __restrict__ b_hh)
{
    __shared__ __align__(16) float x_s[F_ * TRP2];   // x_t transposed+duplicated [f][2r]
    __shared__ __align__(16) float h_s[H_ * TRP2];   // h transposed+duplicated [k][2r]

    const int tid   = threadIdx.x;
    const int rg    = tid >> 5, cg = tid & 31;
    const int row0  = rg * RPT;
    const int row0d = row0 * 2;
    const int c4    = cg * 4;
    const int bn0   = blockIdx.x * TR;

    for (int i = tid; i < H_ * TRP2; i += 256) h_s[i] = 0.0f;

    float br[4], bz[4], bi_n[4], bh_n[4];
    #pragma unroll
    for (int j = 0; j < 4; ++j) {
        br[j]   = b_ih[c4 + j]        + b_hh[c4 + j];
        bz[j]   = b_ih[H_ + c4 + j]   + b_hh[H_ + c4 + j];
        bi_n[j] = b_ih[2 * H_ + c4 + j];
        bh_n[j] = b_hh[2 * H_ + c4 + j];
    }

    for (int t = 0; t < T_; ++t) {
        // load x_t tile (48 rows x 64 f), transposed + duplicated into smem
        #pragma unroll
        for (int u = 0; u < 3; ++u) {
            int idx = tid + u * 256;       // 0..767 float4 slots
            int r = idx >> 4;
            int f = (idx & 15) * 4;
            float4 v = make_float4(0.f, 0.f, 0.f, 0.f);
            int bn = bn0 + r;
            if (bn < BN)
                v = *reinterpret_cast<const float4*>(x + ((size_t)bn * T_ + t) * F_ + f);
            ull p;
            PACK2(p, v.x, v.x); *reinterpret_cast<ull*>(&x_s[(f + 0) * TRP2 + 2 * r]) = p;
            PACK2(p, v.y, v.y); *reinterpret_cast<ull*>(&x_s[(f + 1) * TRP2 + 2 * r]) = p;
            PACK2(p, v.z, v.z); *reinterpret_cast<ull*>(&x_s[(f + 2) * TRP2 + 2 * r]) = p;
            PACK2(p, v.w, v.w); *reinterpret_cast<ull*>(&x_s[(f + 3) * TRP2 + 2 * r]) = p;
        }
        __syncthreads();   // x_s ready; h_s writes from prev step visible

        ull aR[RPT][2], aZ[RPT][2], aNx[RPT][2], aNh[RPT][2];
        ZERO6x2(aR); ZERO6x2(aZ); ZERO6x2(aNx); ZERO6x2(aNh);

        // ---- x-part: gi (all 3 gates), K = 64 ----
        #pragma unroll 4
        for (int k = 0; k < F_; ++k) {
            const float* wrow = g_wihT + (size_t)k * H3_ + c4;
            ulonglong2 w0 = __ldg(reinterpret_cast<const ulonglong2*>(wrow));
            ulonglong2 w1 = __ldg(reinterpret_cast<const ulonglong2*>(wrow + H_));
            ulonglong2 w2 = __ldg(reinterpret_cast<const ulonglong2*>(wrow + 2 * H_));
            const float* ap = x_s + k * TRP2 + row0d;
            ull a2[RPT];
            #pragma unroll
            for (int i = 0; i < RPT; ++i)
                a2[i] = *reinterpret_cast<const ull*>(ap + 2 * i);
            #pragma unroll
            for (int i = 0; i < RPT; ++i) {
                FMA2(aR[i][0],  a2[i], w0.x, aR[i][0]);
                FMA2(aR[i][1],  a2[i], w0.y, aR[i][1]);
                FMA2(aZ[i][0],  a2[i], w1.x, aZ[i][0]);
                FMA2(aZ[i][1],  a2[i], w1.y, aZ[i][1]);
                FMA2(aNx[i][0], a2[i], w2.x, aNx[i][0]);
                FMA2(aNx[i][1], a2[i], w2.y, aNx[i][1]);
            }
        }

        // ---- h-part: gh (r,z joined into aR/aZ; n separate), K = 128 ----
        #pragma unroll 4
        for (int k = 0; k < H_; ++k) {
            const float* wrow = g_whhT + (size_t)k * H3_ + c4;
            ulonglong2 w0 = __ldg(reinterpret_cast<const ulonglong2*>(wrow));
            ulonglong2 w1 = __ldg(reinterpret_cast<const ulonglong2*>(wrow + H_));
            ulonglong2 w2 = __ldg(reinterpret_cast<const ulonglong2*>(wrow + 2 * H_));
            const float* ap = h_s + k * TRP2 + row0d;
            ull a2[RPT];
            #pragma unroll
            for (int i = 0; i < RPT; ++i)
                a2[i] = *reinterpret_cast<const ull*>(ap + 2 * i);
            #pragma unroll
            for (int i = 0; i < RPT; ++i) {
                FMA2(aR[i][0],  a2[i], w0.x, aR[i][0]);
                FMA2(aR[i][1],  a2[i], w0.y, aR[i][1]);
                FMA2(aZ[i][0],  a2[i], w1.x, aZ[i][0]);
                FMA2(aZ[i][1],  a2[i], w1.y, aZ[i][1]);
                FMA2(aNh[i][0], a2[i], w2.x, aNh[i][0]);
                FMA2(aNh[i][1], a2[i], w2.y, aNh[i][1]);
            }
        }

        float fR[RPT][4], fZ[RPT][4], fNx[RPT][4], fNh[RPT][4];
        UNPACK6x2(fR, aR); UNPACK6x2(fZ, aZ);
        UNPACK6x2(fNx, aNx); UNPACK6x2(fNh, aNh);

        float hn[RPT][4];
        #pragma unroll
        for (int i = 0; i < RPT; ++i)
            #pragma unroll
            for (int j = 0; j < 4; ++j) {
                float hold = h_s[(c4 + j) * TRP2 + 2 * (row0 + i)];
                float rr = sigmoidf_(fR[i][j] + br[j]);
                float zz = sigmoidf_(fZ[i][j] + bz[j]);
                float n  = tanhf_(fNx[i][j] + bi_n[j] + rr * (fNh[i][j] + bh_n[j]));
                hn[i][j] = (1.f - zz) * n + zz * hold;
            }
        __syncthreads();   // all reads of h_s / x_s done

        #pragma unroll
        for (int i = 0; i < RPT; ++i) {
            #pragma unroll
            for (int j = 0; j < 4; ++j) {
                ull p;
                PACK2(p, hn[i][j], hn[i][j]);
                *reinterpret_cast<ull*>(&h_s[(c4 + j) * TRP2 + 2 * (row0 + i)]) = p;
            }
            int bn = bn0 + row0 + i;
            if (bn < BN)
                *reinterpret_cast<float4*>(g_seq1 + ((size_t)bn * T_ + t) * H_ + c4)
                    = make_float4(hn[i][0], hn[i][1], hn[i][2], hn[i][3]);
        }
        // next iteration's post-load __syncthreads orders these writes vs. reads
    }
}

// ---------------- Layer 1: custom GRUCell over T steps ----------------
// Fused r,z gate GEMM (lane owns cols c4 and c4+128 of the 256 gate outputs);
// candidate GEMM separate (depends on r).
__global__ __launch_bounds__(256, 1)
void gru_layer1(const float* __restrict__ gate_b,
                const float* __restrict__ out_b,
                float* __restrict__ out)
{
    __shared__ __align__(16) float x_s[H_ * TRP2];
    __shared__ __align__(16) float h_s[H_ * TRP2];
    __shared__ __align__(16) float rh_s[H_ * TRP2];

    const int tid   = threadIdx.x;
    const int rg    = tid >> 5, cg = tid & 31;
    const int row0  = rg * RPT;
    const int row0d = row0 * 2;
    const int c4    = cg * 4;
    const int bn0   = blockIdx.x * TR;

    for (int i = tid; i < H_ * TRP2; i += 256) h_s[i] = 0.0f;

    float bgr[4], bgz[4], bo[4];
    #pragma unroll
    for (int j = 0; j < 4; ++j) {
        bgr[j] = gate_b[c4 + j];
        bgz[j] = gate_b[H_ + c4 + j];
        bo[j]  = out_b[c4 + j];
    }

    for (int t = 0; t < T_; ++t) {
        // load x_t = seq1[:, t, :] tile (48 x 128), transposed + duplicated
        #pragma unroll
        for (int u = 0; u < 6; ++u) {
            int idx = tid + u * 256;    // 0..1535 float4 slots
            int r = idx >> 5;
            int f = (idx & 31) * 4;
            float4 v = make_float4(0.f, 0.f, 0.f, 0.f);
            int bn = bn0 + r;
            if (bn < BN)
                v = *reinterpret_cast<const float4*>(g_seq1 + ((size_t)bn * T_ + t) * H_ + f);
            ull p;
            PACK2(p, v.x, v.x); *reinterpret_cast<ull*>(&x_s[(f + 0) * TRP2 + 2 * r]) = p;
            PACK2(p, v.y, v.y); *reinterpret_cast<ull*>(&x_s[(f + 1) * TRP2 + 2 * r]) = p;
            PACK2(p, v.z, v.z); *reinterpret_cast<ull*>(&x_s[(f + 2) * TRP2 + 2 * r]) = p;
            PACK2(p, v.w, v.w); *reinterpret_cast<ull*>(&x_s[(f + 3) * TRP2 + 2 * r]) = p;
        }
        __syncthreads();

        ull aR[RPT][2], aZ[RPT][2];
        ZERO6x2(aR); ZERO6x2(aZ);

        // ---- gates: x-part (gate_w rows 0..127) ----
        #pragma unroll 4
        for (int k = 0; k < H_; ++k) {
            const float* wrow = g_gwT + (size_t)k * H2_ + c4;
            ulonglong2 w0 = __ldg(reinterpret_cast<const ulonglong2*>(wrow));
            ulonglong2 w1 = __ldg(reinterpret_cast<const ulonglong2*>(wrow + H_));
            const float* ap = x_s + k * TRP2 + row0d;
            ull a2[RPT];
            #pragma unroll
            for (int i = 0; i < RPT; ++i)
                a2[i] = *reinterpret_cast<const ull*>(ap + 2 * i);
            #pragma unroll
            for (int i = 0; i < RPT; ++i) {
                FMA2(aR[i][0], a2[i], w0.x, aR[i][0]);
                FMA2(aR[i][1], a2[i], w0.y, aR[i][1]);
                FMA2(aZ[i][0], a2[i], w1.x, aZ[i][0]);
                FMA2(aZ[i][1], a2[i], w1.y, aZ[i][1]);
            }
        }
        // ---- gates: h-part (gate_w rows 128..255) ----
        #pragma unroll 4
        for (int k = 0; k < H_; ++k) {
            const float* wrow = g_gwT + (size_t)(H_ + k) * H2_ + c4;
            ulonglong2 w0 = __ldg(reinterpret_cast<const ulonglong2*>(wrow));
            ulonglong2 w1 = __ldg(reinterpret_cast<const ulonglong2*>(wrow + H_));
            const float* ap = h_s + k * TRP2 + row0d;
            ull a2[RPT];
            #pragma unroll
            for (int i = 0; i < RPT; ++i)
                a2[i] = *reinterpret_cast<const ull*>(ap + 2 * i);
            #pragma unroll
            for (int i = 0; i < RPT; ++i) {
                FMA2(aR[i][0], a2[i], w0.x, aR[i][0]);
                FMA2(aR[i][1], a2[i], w0.y, aR[i][1]);
                FMA2(aZ[i][0], a2[i], w1.x, aZ[i][0]);
                FMA2(aZ[i][1], a2[i], w1.y, aZ[i][1]);
            }
        }

        float fR[RPT][4], fZ[RPT][4];
        UNPACK6x2(fR, aR); UNPACK6x2(fZ, aZ);

        // r * h into smem (thread's r-cols == its h-feature cols)
        float hold[RPT][4], zz[RPT][4];
        #pragma unroll
        for (int i = 0; i < RPT; ++i)
            #pragma unroll
            for (int j = 0; j < 4; ++j) {
                hold[i][j] = h_s[(c4 + j) * TRP2 + 2 * (row0 + i)];
                zz[i][j] = sigmoidf_(fZ[i][j] + bgz[j]);
                float rr = sigmoidf_(fR[i][j] + bgr[j]);
                float rh = rr * hold[i][j];
                ull p;
                PACK2(p, rh, rh);
                *reinterpret_cast<ull*>(&rh_s[(c4 + j) * TRP2 + 2 * (row0 + i)]) = p;
            }
        __syncthreads();   // rh_s ready; all h_s reads done

        // candidate: [x | r*h] @ out_w^T  (cols 0..127)
        ull aC[RPT][2];
        ZERO6x2(aC);
        #pragma unroll 4
        for (int k = 0; k < H_; ++k) {
            ulonglong2 w0 = __ldg(reinterpret_cast<const ulonglong2*>(
                g_owT + (size_t)k * H_ + c4));
            const float* ap = x_s + k * TRP2 + row0d;
            ull a2[RPT];
            #pragma unroll
            for (int i = 0; i < RPT; ++i)
                a2[i] = *reinterpret_cast<const ull*>(ap + 2 * i);
            #pragma unroll
            for (int i = 0; i < RPT; ++i) {
                FMA2(aC[i][0], a2[i], w0.x, aC[i][0]);
                FMA2(aC[i][1], a2[i], w0.y, aC[i][1]);
            }
        }
        #pragma unroll 4
        for (int k = 0; k < H_; ++k) {
            ulonglong2 w0 = __ldg(reinterpret_cast<const ulonglong2*>(
                g_owT + (size_t)(H_ + k) * H_ + c4));
            const float* ap = rh_s + k * TRP2 + row0d;
            ull a2[RPT];
            #pragma unroll
            for (int i = 0; i < RPT; ++i)
                a2[i] = *reinterpret_cast<const ull*>(ap + 2 * i);
            #pragma unroll
            for (int i = 0; i < RPT; ++i) {
                FMA2(aC[i][0], a2[i], w0.x, aC[i][0]);
                FMA2(aC[i][1], a2[i], w0.y, aC[i][1]);
            }
        }

        float fC[RPT][4];
        UNPACK6x2(fC, aC);

        float hn[RPT][4];
        #pragma unroll
        for (int i = 0; i < RPT; ++i)
            #pragma unroll
            for (int j = 0; j < 4; ++j) {
                float cand = tanhf_(fC[i][j] + bo[j]);
                hn[i][j] = zz[i][j] * hold[i][j] + (1.f - zz[i][j]) * cand;
            }
        __syncthreads();   // all x_s / rh_s reads done before overwrites

        #pragma unroll
        for (int i = 0; i < RPT; ++i) {
            #pragma unroll
            for (int j = 0; j < 4; ++j) {
                ull p;
                PACK2(p, hn[i][j], hn[i][j]);
                *reinterpret_cast<ull*>(&h_s[(c4 + j) * TRP2 + 2 * (row0 + i)]) = p;
            }
            int bn = bn0 + row0 + i;
            if (bn < BN)
                *reinterpret_cast<float4*>(out + ((size_t)bn * T_ + t) * H_ + c4)
                    = make_float4(hn[i][0], hn[i][1], hn[i][2], hn[i][3]);
        }
    }
}

extern "C" void kernel_launch(void* const* d_in, const int* in_sizes, int n_in,
                              void* d_out, int out_size)
{
    const float* x      = (const float*)d_in[0];
    const float* w_ih   = (const float*)d_in[1];
    const float* w_hh   = (const float*)d_in[2];
    const float* b_ih   = (const float*)d_in[3];
    const float* b_hh   = (const float*)d_in[4];
    const float* gate_w = (const float*)d_in[5];
    const float* gate_b = (const float*)d_in[6];
    const float* out_w  = (const float*)d_in[7];
    const float* out_b  = (const float*)d_in[8];
    float* out = (float*)d_out;

    transpose_weights<<<(H2_ * H2_ + 255) / 256, 256>>>(w_ih, w_hh, gate_w, out_w);
    gru_layer0<<<NCTA, 256>>>(x, b_ih, b_hh);
    gru_layer1<<<NCTA, 256>>>(gate_b, out_b, out);
}

// round 5
// speedup vs baseline: 1.1040x; 1.0011x over previous
#include <cuda_runtime.h>
#include <math.h>

#define BN   20800
#define T_   24
#define F_   64
#define H_   128
#define H2_  256
#define H3_  384
#define TR   48            // rows per CTA
#define TRP2 98            // padded duplicated smem row stride (2*TR + 2, even)
#define RPT  6             // rows per thread
#define NCTA ((BN + TR - 1) / TR)   // 434

typedef unsigned long long ull;

// packed f32x2 FMA: d = a*b + c elementwise on two packed fp32
#define FMA2(d, a, b, c) \
    asm("fma.rn.f32x2 %0, %1, %2, %3;" : "=l"(d) : "l"(a), "l"(b), "l"(c))
#define UNPK2(lo, hi, v) \
    asm("mov.b64 {%0, %1}, %2;" : "=f"(lo), "=f"(hi) : "l"(v))
#define PACK2(d, lo, hi) \
    asm("mov.b64 %0, {%1, %2};" : "=l"(d) : "f"(lo), "f"(hi))

// scratch: layer-0 output sequence [BN][T][H]
__device__ float g_seq1[(size_t)BN * T_ * H_];
// pre-transposed weights: [k][c]
__device__ float g_wihT[F_ * H3_];
__device__ float g_whhT[H_ * H3_];
__device__ float g_gwT[H2_ * H2_];
__device__ float g_owT[H2_ * H_];

__global__ void transpose_weights(const float* __restrict__ w_ih,
                                  const float* __restrict__ w_hh,
                                  const float* __restrict__ gate_w,
                                  const float* __restrict__ out_w)
{
    int idx = blockIdx.x * blockDim.x + threadIdx.x;
    if (idx < H3_ * F_)  { int c = idx / F_,  k = idx % F_;  g_wihT[k * H3_ + c] = w_ih[idx]; }
    if (idx < H3_ * H_)  { int c = idx / H_,  k = idx % H_;  g_whhT[k * H3_ + c] = w_hh[idx]; }
    if (idx < H2_ * H2_) { int c = idx / H2_, k = idx % H2_; g_gwT[k * H2_ + c] = gate_w[idx]; }
    if (idx < H_ * H2_)  { int c = idx / H2_, k = idx % H2_; g_owT[k * H_ + c] = out_w[idx]; }
}

__device__ __forceinline__ float sigmoidf_(float v) {
    return __fdividef(1.0f, 1.0f + __expf(-v));
}
__device__ __forceinline__ float tanhf_(float v) {
    return __fdividef(2.0f, 1.0f + __expf(-2.0f * v)) - 1.0f;
}

#define ZERO6x2(A)                                    \
    _Pragma("unroll")                                 \
    for (int i = 0; i < RPT; ++i) {                   \
        (A)[i][0] = 0ULL; (A)[i][1] = 0ULL;           \
    }

#define UNPACK6x2(F, A)                               \
    _Pragma("unroll")                                 \
    for (int i = 0; i < RPT; ++i) {                   \
        UNPK2((F)[i][0], (F)[i][1], (A)[i][0]);       \
        UNPK2((F)[i][2], (F)[i][3], (A)[i][1]);       \
    }

// ---------------- Layer 0: torch GRUCell over T steps ----------------
// Fused-gate GEMM: one pass over x (K=64) and one over h (K=128); each k
// loads the activation ONCE (6 broadcast LDS.64) and three weight float4s
// (r/z/n column blocks). r,z accumulate x+h jointly; n kept split.
__global__ __launch_bounds__(256, 1)
void gru_layer0(const float* __restrict__ x,
                const float* __restrict__ b_ih,
                const float* __restrict__ b_hh)
{
    __shared__ __align__(16) float x_s[F_ * TRP2];   // x_t transposed+duplicated [f][2r]
    __shared__ __align__(16) float h_s[H_ * TRP2];   // h transposed+duplicated [k][2r]

    const int tid   = threadIdx.x;
    const int rg    = tid >> 5, cg = tid & 31;
    const int row0  = rg * RPT;
    const int row0d = row0 * 2;
    const int c4    = cg * 4;
    const int bn0   = blockIdx.x * TR;

    for (int i = tid; i < H_ * TRP2; i += 256) h_s[i] = 0.0f;

    float br[4], bz[4], bi_n[4], bh_n[4];
    #pragma unroll
    for (int j = 0; j < 4; ++j) {
        br[j]   = b_ih[c4 + j]        + b_hh[c4 + j];
        bz[j]   = b_ih[H_ + c4 + j]   + b_hh[H_ + c4 + j];
        bi_n[j] = b_ih[2 * H_ + c4 + j];
        bh_n[j] = b_hh[2 * H_ + c4 + j];
    }

    for (int t = 0; t < T_; ++t) {
        // load x_t tile (48 rows x 64 f), transposed + duplicated into smem
        #pragma unroll
        for (int u = 0; u < 3; ++u) {
            int idx = tid + u * 256;       // 0..767 float4 slots
            int r = idx >> 4;
            int f = (idx & 15) * 4;
            float4 v = make_float4(0.f, 0.f, 0.f, 0.f);
            int bn = bn0 + r;
            if (bn < BN)
                v = *reinterpret_cast<const float4*>(x + ((size_t)bn * T_ + t) * F_ + f);
            ull p;
            PACK2(p, v.x, v.x); *reinterpret_cast<ull*>(&x_s[(f + 0) * TRP2 + 2 * r]) = p;
            PACK2(p, v.y, v.y); *reinterpret_cast<ull*>(&x_s[(f + 1) * TRP2 + 2 * r]) = p;
            PACK2(p, v.z, v.z); *reinterpret_cast<ull*>(&x_s[(f + 2) * TRP2 + 2 * r]) = p;
            PACK2(p, v.w, v.w); *reinterpret_cast<ull*>(&x_s[(f + 3) * TRP2 + 2 * r]) = p;
        }
        __syncthreads();   // x_s ready; h_s writes from prev step visible

        ull aR[RPT][2], aZ[RPT][2], aNx[RPT][2], aNh[RPT][2];
        ZERO6x2(aR); ZERO6x2(aZ); ZERO6x2(aNx); ZERO6x2(aNh);

        // ---- x-part: gi (all 3 gates), K = 64 ----
        #pragma unroll 4
        for (int k = 0; k < F_; ++k) {
            const float* wrow = g_wihT + (size_t)k * H3_ + c4;
            ulonglong2 w0 = __ldg(reinterpret_cast<const ulonglong2*>(wrow));
            ulonglong2 w1 = __ldg(reinterpret_cast<const ulonglong2*>(wrow + H_));
            ulonglong2 w2 = __ldg(reinterpret_cast<const ulonglong2*>(wrow + 2 * H_));
            const float* ap = x_s + k * TRP2 + row0d;
            ull a2[RPT];
            #pragma unroll
            for (int i = 0; i < RPT; ++i)
                a2[i] = *reinterpret_cast<const ull*>(ap + 2 * i);
            #pragma unroll
            for (int i = 0; i < RPT; ++i) {
                FMA2(aR[i][0],  a2[i], w0.x, aR[i][0]);
                FMA2(aR[i][1],  a2[i], w0.y, aR[i][1]);
                FMA2(aZ[i][0],  a2[i], w1.x, aZ[i][0]);
                FMA2(aZ[i][1],  a2[i], w1.y, aZ[i][1]);
                FMA2(aNx[i][0], a2[i], w2.x, aNx[i][0]);
                FMA2(aNx[i][1], a2[i], w2.y, aNx[i][1]);
            }
        }

        // ---- h-part: gh (r,z joined into aR/aZ; n separate), K = 128 ----
        #pragma unroll 4
        for (int k = 0; k < H_; ++k) {
            const float* wrow = g_whhT + (size_t)k * H3_ + c4;
            ulonglong2 w0 = __ldg(reinterpret_cast<const ulonglong2*>(wrow));
            ulonglong2 w1 = __ldg(reinterpret_cast<const ulonglong2*>(wrow + H_));
            ulonglong2 w2 = __ldg(reinterpret_cast<const ulonglong2*>(wrow + 2 * H_));
            const float* ap = h_s + k * TRP2 + row0d;
            ull a2[RPT];
            #pragma unroll
            for (int i = 0; i < RPT; ++i)
                a2[i] = *reinterpret_cast<const ull*>(ap + 2 * i);
            #pragma unroll
            for (int i = 0; i < RPT; ++i) {
                FMA2(aR[i][0],  a2[i], w0.x, aR[i][0]);
                FMA2(aR[i][1],  a2[i], w0.y, aR[i][1]);
                FMA2(aZ[i][0],  a2[i], w1.x, aZ[i][0]);
                FMA2(aZ[i][1],  a2[i], w1.y, aZ[i][1]);
                FMA2(aNh[i][0], a2[i], w2.x, aNh[i][0]);
                FMA2(aNh[i][1], a2[i], w2.y, aNh[i][1]);
            }
        }

        float fR[RPT][4], fZ[RPT][4], fNx[RPT][4], fNh[RPT][4];
        UNPACK6x2(fR, aR); UNPACK6x2(fZ, aZ);
        UNPACK6x2(fNx, aNx); UNPACK6x2(fNh, aNh);

        float hn[RPT][4];
        #pragma unroll
        for (int i = 0; i < RPT; ++i)
            #pragma unroll
            for (int j = 0; j < 4; ++j) {
                float hold = h_s[(c4 + j) * TRP2 + 2 * (row0 + i)];
                float rr = sigmoidf_(fR[i][j] + br[j]);
                float zz = sigmoidf_(fZ[i][j] + bz[j]);
                float n  = tanhf_(fNx[i][j] + bi_n[j] + rr * (fNh[i][j] + bh_n[j]));
                hn[i][j] = (1.f - zz) * n + zz * hold;
            }
        __syncthreads();   // all reads of h_s / x_s done

        #pragma unroll
        for (int i = 0; i < RPT; ++i) {
            #pragma unroll
            for (int j = 0; j < 4; ++j) {
                ull p;
                PACK2(p, hn[i][j], hn[i][j]);
                *reinterpret_cast<ull*>(&h_s[(c4 + j) * TRP2 + 2 * (row0 + i)]) = p;
            }
            int bn = bn0 + row0 + i;
            if (bn < BN)
                *reinterpret_cast<float4*>(g_seq1 + ((size_t)bn * T_ + t) * H_ + c4)
                    = make_float4(hn[i][0], hn[i][1], hn[i][2], hn[i][3]);
        }
        // next iteration's post-load __syncthreads orders these writes vs. reads
    }
}

// ---------------- Layer 1: custom GRUCell over T steps ----------------
// Fused r,z gate GEMM (lane owns cols c4 and c4+128 of the 256 gate outputs);
// candidate GEMM separate (depends on r).
__global__ __launch_bounds__(256, 1)
void gru_layer1(const float* __restrict__ gate_b,
                const float* __restrict__ out_b,
                float* __restrict__ out)
{
    __shared__ __align__(16) float x_s[H_ * TRP2];
    __shared__ __align__(16) float h_s[H_ * TRP2];
    __shared__ __align__(16) float rh_s[H_ * TRP2];

    const int tid   = threadIdx.x;
    const int rg    = tid >> 5, cg = tid & 31;
    const int row0  = rg * RPT;
    const int row0d = row0 * 2;
    const int c4    = cg * 4;
    const int bn0   = blockIdx.x * TR;

    for (int i = tid; i < H_ * TRP2; i += 256) h_s[i] = 0.0f;

    float bgr[4], bgz[4], bo[4];
    #pragma unroll
    for (int j = 0; j < 4; ++j) {
        bgr[j] = gate_b[c4 + j];
        bgz[j] = gate_b[H_ + c4 + j];
        bo[j]  = out_b[c4 + j];
    }

    for (int t = 0; t < T_; ++t) {
        // load x_t = seq1[:, t, :] tile (48 x 128), transposed + duplicated
        #pragma unroll
        for (int u = 0; u < 6; ++u) {
            int idx = tid + u * 256;    // 0..1535 float4 slots
            int r = idx >> 5;
            int f = (idx & 31) * 4;
            float4 v = make_float4(0.f, 0.f, 0.f, 0.f);
            int bn = bn0 + r;
            if (bn < BN)
                v = *reinterpret_cast<const float4*>(g_seq1 + ((size_t)bn * T_ + t) * H_ + f);
            ull p;
            PACK2(p, v.x, v.x); *reinterpret_cast<ull*>(&x_s[(f + 0) * TRP2 + 2 * r]) = p;
            PACK2(p, v.y, v.y); *reinterpret_cast<ull*>(&x_s[(f + 1) * TRP2 + 2 * r]) = p;
            PACK2(p, v.z, v.z); *reinterpret_cast<ull*>(&x_s[(f + 2) * TRP2 + 2 * r]) = p;
            PACK2(p, v.w, v.w); *reinterpret_cast<ull*>(&x_s[(f + 3) * TRP2 + 2 * r]) = p;
        }
        __syncthreads();

        ull aR[RPT][2], aZ[RPT][2];
        ZERO6x2(aR); ZERO6x2(aZ);

        // ---- gates: x-part (gate_w rows 0..127) ----
        #pragma unroll 4
        for (int k = 0; k < H_; ++k) {
            const float* wrow = g_gwT + (size_t)k * H2_ + c4;
            ulonglong2 w0 = __ldg(reinterpret_cast<const ulonglong2*>(wrow));
            ulonglong2 w1 = __ldg(reinterpret_cast<const ulonglong2*>(wrow + H_));
            const float* ap = x_s + k * TRP2 + row0d;
            ull a2[RPT];
            #pragma unroll
            for (int i = 0; i < RPT; ++i)
                a2[i] = *reinterpret_cast<const ull*>(ap + 2 * i);
            #pragma unroll
            for (int i = 0; i < RPT; ++i) {
                FMA2(aR[i][0], a2[i], w0.x, aR[i][0]);
                FMA2(aR[i][1], a2[i], w0.y, aR[i][1]);
                FMA2(aZ[i][0], a2[i], w1.x, aZ[i][0]);
                FMA2(aZ[i][1], a2[i], w1.y, aZ[i][1]);
            }
        }
        // ---- gates: h-part (gate_w rows 128..255) ----
        #pragma unroll 4
        for (int k = 0; k < H_; ++k) {
            const float* wrow = g_gwT + (size_t)(H_ + k) * H2_ + c4;
            ulonglong2 w0 = __ldg(reinterpret_cast<const ulonglong2*>(wrow));
            ulonglong2 w1 = __ldg(reinterpret_cast<const ulonglong2*>(wrow + H_));
            const float* ap = h_s + k * TRP2 + row0d;
            ull a2[RPT];
            #pragma unroll
            for (int i = 0; i < RPT; ++i)
                a2[i] = *reinterpret_cast<const ull*>(ap + 2 * i);
            #pragma unroll
            for (int i = 0; i < RPT; ++i) {
                FMA2(aR[i][0], a2[i], w0.x, aR[i][0]);
                FMA2(aR[i][1], a2[i], w0.y, aR[i][1]);
                FMA2(aZ[i][0], a2[i], w1.x, aZ[i][0]);
                FMA2(aZ[i][1], a2[i], w1.y, aZ[i][1]);
            }
        }

        float fR[RPT][4], fZ[RPT][4];
        UNPACK6x2(fR, aR); UNPACK6x2(fZ, aZ);

        // r * h into smem (thread's r-cols == its h-feature cols)
        float hold[RPT][4], zz[RPT][4];
        #pragma unroll
        for (int i = 0; i < RPT; ++i)
            #pragma unroll
            for (int j = 0; j < 4; ++j) {
                hold[i][j] = h_s[(c4 + j) * TRP2 + 2 * (row0 + i)];
                zz[i][j] = sigmoidf_(fZ[i][j] + bgz[j]);
                float rr = sigmoidf_(fR[i][j] + bgr[j]);
                float rh = rr * hold[i][j];
                ull p;
                PACK2(p, rh, rh);
                *reinterpret_cast<ull*>(&rh_s[(c4 + j) * TRP2 + 2 * (row0 + i)]) = p;
            }
        __syncthreads();   // rh_s ready; all h_s reads done

        // candidate: [x | r*h] @ out_w^T  (cols 0..127)
        ull aC[RPT][2];
        ZERO6x2(aC);
        #pragma unroll 4
        for (int k = 0; k < H_; ++k) {
            ulonglong2 w0 = __ldg(reinterpret_cast<const ulonglong2*>(
                g_owT + (size_t)k * H_ + c4));
            const float* ap = x_s + k * TRP2 + row0d;
            ull a2[RPT];
            #pragma unroll
            for (int i = 0; i < RPT; ++i)
                a2[i] = *reinterpret_cast<const ull*>(ap + 2 * i);
            #pragma unroll
            for (int i = 0; i < RPT; ++i) {
                FMA2(aC[i][0], a2[i], w0.x, aC[i][0]);
                FMA2(aC[i][1], a2[i], w0.y, aC[i][1]);
            }
        }
        #pragma unroll 4
        for (int k = 0; k < H_; ++k) {
            ulonglong2 w0 = __ldg(reinterpret_cast<const ulonglong2*>(
                g_owT + (size_t)(H_ + k) * H_ + c4));
            const float* ap = rh_s + k * TRP2 + row0d;
            ull a2[RPT];
            #pragma unroll
            for (int i = 0; i < RPT; ++i)
                a2[i] = *reinterpret_cast<const ull*>(ap + 2 * i);
            #pragma unroll
            for (int i = 0; i < RPT; ++i) {
                FMA2(aC[i][0], a2[i], w0.x, aC[i][0]);
                FMA2(aC[i][1], a2[i], w0.y, aC[i][1]);
            }
        }

        float fC[RPT][4];
        UNPACK6x2(fC, aC);

        float hn[RPT][4];
        #pragma unroll
        for (int i = 0; i < RPT; ++i)
            #pragma unroll
            for (int j = 0; j < 4; ++j) {
                float cand = tanhf_(fC[i][j] + bo[j]);
                hn[i][j] = zz[i][j] * hold[i][j] + (1.f - zz[i][j]) * cand;
            }
        __syncthreads();   // all x_s / rh_s reads done before overwrites

        #pragma unroll
        for (int i = 0; i < RPT; ++i) {
            #pragma unroll
            for (int j = 0; j < 4; ++j) {
                ull p;
                PACK2(p, hn[i][j], hn[i][j]);
                *reinterpret_cast<ull*>(&h_s[(c4 + j) * TRP2 + 2 * (row0 + i)]) = p;
            }
            int bn = bn0 + row0 + i;
            if (bn < BN)
                *reinterpret_cast<float4*>(out + ((size_t)bn * T_ + t) * H_ + c4)
                    = make_float4(hn[i][0], hn[i][1], hn[i][2], hn[i][3]);
        }
    }
}

extern "C" void kernel_launch(void* const* d_in, const int* in_sizes, int n_in,
                              void* d_out, int out_size)
{
    const float* x      = (const float*)d_in[0];
    const float* w_ih   = (const float*)d_in[1];
    const float* w_hh   = (const float*)d_in[2];
    const float* b_ih   = (const float*)d_in[3];
    const float* b_hh   = (const float*)d_in[4];
    const float* gate_w = (const float*)d_in[5];
    const float* gate_b = (const float*)d_in[6];
    const float* out_w  = (const float*)d_in[7];
    const float* out_b  = (const float*)d_in[8];
    float* out = (float*)d_out;

    transpose_weights<<<(H2_ * H2_ + 255) / 256, 256>>>(w_ih, w_hh, gate_w, out_w);
    gru_layer0<<<NCTA, 256>>>(x, b_ih, b_hh);
    gru_layer1<<<NCTA, 256>>>(gate_b, out_b, out);
}